// round 2
// baseline (speedup 1.0000x reference)
#include <cuda_runtime.h>
#include <cuda_bf16.h>

// Problem constants (fixed by the reference)
#define BB      16
#define SS      512
#define NH      8
#define M_BLOOM 4096
#define WW      2
#define KBLK    (2 * WW + 1)        // 5
#define TJ      32                  // j-tile width (floats); 32*4B = 128B rows
#define NT      (SS / TJ)           // 16 tiles
#define NCOL    (TJ + 2 * WW)       // 36 fc-columns needed per tile
#define THREADS 512

// One CTA owns out[b, :, j0 : j0+TJ] for all 5*4096 rows.
// Phase 1: zero the slab (write-only, 128B sector-aligned row segments).
// Phase 2: patch the <=NCOL*NH*5 nonzero entries; counts computed by direct
//          8x8 fingerprint comparison per column (duplicate patches are
//          idempotent: they write the same count).
__global__ void __launch_bounds__(THREADS) bloom_fused_kernel(
        const int* __restrict__ hashes, float* __restrict__ out) {
    const int tile = blockIdx.x;          // 0..NT-1
    const int b    = blockIdx.y;          // 0..BB-1
    const int j0   = tile * TJ;
    const int t    = threadIdx.x;

    __shared__ int fpv[NCOL][NH];

    // Stage this tile's fingerprints (issued early so loads overlap phase 1).
    if (t < NCOL * NH) {
        const int c = t / NH, n = t % NH;
        const int s = j0 - WW + c;        // fc column index in [j0-2, j0+TJ+2)
        int v = -1;
        if (s >= 0 && s < SS)
            v = hashes[(b * SS + s) * NH + n] & (M_BLOOM - 1);  // h >= 0
        fpv[c][n] = v;
    }

    // ---- Phase 1: zero the slab ----------------------------------------
    // Rows R in [R0, R0 + KBLK*M_BLOOM); each row contributes TJ floats
    // (= 8 float4) starting at column j0. 8 threads per row, 64 rows/iter.
    const long long R0 = (long long)b * KBLK * M_BLOOM;
    float4* p = (float4*)(out + (R0 + (t >> 3)) * SS + j0) + (t & 7);
    const float4 z = make_float4(0.f, 0.f, 0.f, 0.f);
    // total rows = KBLK*M_BLOOM = 20480; 64 rows/iter -> 320 iters; unroll 16.
#pragma unroll 1
    for (int it = 0; it < (KBLK * M_BLOOM) / 64 / 16; ++it) {
#pragma unroll
        for (int u = 0; u < 16; ++u)
            p[(long long)u * 64 * (SS / 4)] = z;   // compile-time imm offsets
        p += (long long)16 * 64 * (SS / 4);
    }

    __syncthreads();   // orders phase-1 global stores before phase-2 stores

    // ---- Phase 2: patch nonzeros ---------------------------------------
    if (t < NCOL * NH) {
        const int c = t / NH, n = t % NH;
        const int m = fpv[c][n];
        if (m >= 0) {
            int cnt = 0;
#pragma unroll
            for (int n2 = 0; n2 < NH; ++n2) cnt += (fpv[c][n2] == m);
            const float v = (float)cnt;
            // out[b, k*M+m, j0+c-k] = fc[m, c]   for valid k
            int kmin = c - (TJ - 1); if (kmin < 0) kmin = 0;
            int kmax = (c < KBLK - 1) ? c : (KBLK - 1);
            for (int k = kmin; k <= kmax; ++k) {
                const long long row = R0 + (long long)k * M_BLOOM + m;
                out[row * SS + j0 + c - k] = v;
            }
        }
    }
}

extern "C" void kernel_launch(void* const* d_in, const int* in_sizes, int n_in,
                              void* d_out, int out_size) {
    const int* hashes = (const int*)d_in[0];
    float* out = (float*)d_out;

    dim3 grid(NT, BB);            // 16 x 16 = 256 CTAs, all co-resident
    bloom_fused_kernel<<<grid, THREADS>>>(hashes, out);
}

// round 3
// speedup vs baseline: 1.2178x; 1.2178x over previous
#include <cuda_runtime.h>
#include <cuda_bf16.h>

// Problem constants (fixed by the reference)
#define BB      16
#define SS      512
#define NH      8
#define MB      4096
#define KBLK    5                    // 2*W+1
#define MRANGE  256                  // rows per slab
#define NSLAB   (BB * KBLK * (MB / MRANGE))   // 16*5*16 = 1280
#define NCTA    296                  // 148 SMs * 2, exactly balanced residency
#define THREADS 512
#define CAP     32                   // max (s,n) entries per (b,m) bucket

// Persistent-CTA kernel. Each slab = 256 consecutive output rows of one
// (b, k) block. Build smem buckets of hash positions hitting the slab's
// m-range, then stream the slab with final values composed in registers.
__global__ void __launch_bounds__(THREADS) bloom_direct_kernel(
        const int* __restrict__ hashes, float* __restrict__ out) {
    __shared__ int cnt[MRANGE];
    __shared__ unsigned short sv[MRANGE][CAP];

    const int t   = threadIdx.x;
    const int rl0 = t >> 7;          // 0..3  (row lane within 4-row group)
    const int c4  = t & 127;         // float4 column within row

    for (int slab = blockIdx.x; slab < NSLAB; slab += NCTA) {
        const int m0 = (slab & 15) * MRANGE;
        const int k  = (slab >> 4) % KBLK;
        const int b  = slab / (KBLK * (MB / MRANGE));   // slab / 80

        // ---- build buckets for this slab's m-range -----------------------
        if (t < MRANGE) cnt[t] = 0;
        __syncthreads();
        {
            // thread t holds the NH hashes of sentence position s = t
            const int4* hp = (const int4*)(hashes + b * SS * NH) + t * 2;
            const int4 h0 = hp[0];
            const int4 h1 = hp[1];
            const int mm[8] = {h0.x & (MB - 1), h0.y & (MB - 1),
                               h0.z & (MB - 1), h0.w & (MB - 1),
                               h1.x & (MB - 1), h1.y & (MB - 1),
                               h1.z & (MB - 1), h1.w & (MB - 1)};
#pragma unroll
            for (int n = 0; n < NH; ++n) {
                const unsigned r = (unsigned)(mm[n] - m0);
                if (r < MRANGE) {
                    const int p = atomicAdd(&cnt[r], 1);
                    if (p < CAP) sv[r][p] = (unsigned short)t;   // s = t
                }
            }
        }
        __syncthreads();

        // ---- stream the slab: 256 rows x 512 floats ----------------------
        // out[row, j] where row = (b*KBLK + k)*MB + m0 + r, value at j is the
        // number of bucket entries s with s + (2-k) == j.
        const int sh    = 2 - k;
        const int jbase = c4 << 2;
        float4* p = (float4*)out +
            (((long long)(b * KBLK + k) * MB + m0 + rl0) * (SS / 4)) + c4;

#pragma unroll 1
        for (int it = 0; it < MRANGE / 16; ++it) {      // 16 iters
#pragma unroll
            for (int u = 0; u < 4; ++u) {
                const int step = it * 4 + u;            // 0..63
                const int r    = rl0 + step * 4;        // whole warp same r
                float4 v = make_float4(0.f, 0.f, 0.f, 0.f);
                int n = cnt[r];
                n = (n < CAP) ? n : CAP;
                for (int e = 0; e < n; ++e) {
                    const int j = (int)sv[r][e] + sh - jbase;
                    if      (j == 0) v.x += 1.f;
                    else if (j == 1) v.y += 1.f;
                    else if (j == 2) v.z += 1.f;
                    else if (j == 3) v.w += 1.f;
                }
                __stcs(p + (long long)step * 4 * (SS / 4), v);
            }
        }
        __syncthreads();   // protect cnt/sv before next slab's rebuild
    }
}

extern "C" void kernel_launch(void* const* d_in, const int* in_sizes, int n_in,
                              void* d_out, int out_size) {
    const int* hashes = (const int*)d_in[0];
    float* out = (float*)d_out;
    bloom_direct_kernel<<<NCTA, THREADS>>>(hashes, out);
}

// round 4
// speedup vs baseline: 1.4389x; 1.1815x over previous
#include <cuda_runtime.h>
#include <cuda_bf16.h>

// Problem constants (fixed by the reference)
#define BB      16
#define SS      512
#define NH      8
#define MB      4096
#define KBLK    5                       // 2*W+1
#define MRANGE  64                      // rows per slab -> 64*2KB = 128KB contiguous
#define NSLAB   (BB * KBLK * (MB / MRANGE))   // 16*5*64 = 5120
#define THREADS 512

// One CTA per slab = 64 contiguous output rows of one (b,k) block.
// Phase 1: zero the contiguous 128KB slab (dependency-free stores).
// Phase 2: thread t (= sentence position s) patches its in-range hashes with
//          counts computed by 8-way register comparison. __syncthreads()
//          (CTA-scope memory fence) orders phase-1 stores before patches.
__global__ void __launch_bounds__(THREADS) bloom_zp_kernel(
        const int* __restrict__ hashes, float* __restrict__ out) {
    const int slab = blockIdx.x;
    const int m0   = (slab & 63) * MRANGE;          // 64 slabs per (b,k)
    const int k    = (slab >> 6) % KBLK;
    const int b    = slab / (KBLK * (MB / MRANGE)); // slab / 320
    const int t    = threadIdx.x;

    // Issue the hash loads early; results consumed after phase 1.
    const int4* hp = (const int4*)(hashes + (b * SS + t) * NH);
    const int4 h0 = __ldg(hp);
    const int4 h1 = __ldg(hp + 1);

    // Slab base: row (b*KBLK + k)*MB + m0, column 0.
    float* const slab_base =
        out + ((long long)(b * KBLK + k) * MB + m0) * SS;

    // ---- Phase 1: zero 32768 float4 = 128KB, contiguous -----------------
    {
        float4* p = (float4*)slab_base + t;
        const float4 z = make_float4(0.f, 0.f, 0.f, 0.f);
#pragma unroll 1
        for (int it = 0; it < (MRANGE * SS / 4) / THREADS / 16; ++it) {
#pragma unroll
            for (int u = 0; u < 16; ++u)
                p[u * THREADS] = z;          // compile-time imm offsets
            p += 16 * THREADS;
        }
    }

    __syncthreads();   // order phase-1 stores before phase-2 patch stores

    // ---- Phase 2: patch nonzeros from registers -------------------------
    const int j = t + 2 - k;               // output column for s = t
    if (j >= 0 && j < SS) {
        const int mm[8] = {h0.x & (MB - 1), h0.y & (MB - 1),
                           h0.z & (MB - 1), h0.w & (MB - 1),
                           h1.x & (MB - 1), h1.y & (MB - 1),
                           h1.z & (MB - 1), h1.w & (MB - 1)};
#pragma unroll
        for (int n = 0; n < NH; ++n) {
            const unsigned r = (unsigned)(mm[n] - m0);
            if (r < MRANGE) {
                int cnt = 0;
#pragma unroll
                for (int n2 = 0; n2 < NH; ++n2) cnt += (mm[n2] == mm[n]);
                // duplicates write the same value -> idempotent
                slab_base[(long long)r * SS + j] = (float)cnt;
            }
        }
    }
}

extern "C" void kernel_launch(void* const* d_in, const int* in_sizes, int n_in,
                              void* d_out, int out_size) {
    const int* hashes = (const int*)d_in[0];
    float* out = (float*)d_out;
    bloom_zp_kernel<<<NSLAB, THREADS>>>(hashes, out);
}

// round 5
// speedup vs baseline: 1.4632x; 1.0169x over previous
#include <cuda_runtime.h>
#include <cuda_bf16.h>

// Problem constants (fixed by the reference)
#define BB      16
#define SS      512
#define NH      8
#define MB      4096
#define KBLK    5                       // 2*W+1
#define MRANGE  32                      // rows per slab -> 32*2KB = 64KB contiguous
#define SPB     (MB / MRANGE)           // 128 slabs per (b,k) block
#define NSLAB   (BB * KBLK * SPB)       // 16*5*128 = 10240
#define THREADS 512

// One CTA per slab = 32 contiguous output rows of one (b,k) block.
// Phase 1: zero the contiguous 64KB slab (8 dependency-free STG.128/thread).
// Phase 2: thread t (= sentence position s) patches its in-range hashes with
//          counts from 8-way register comparison. __syncthreads() (CTA-scope
//          memory fence) orders phase-1 stores before patch stores; patches
//          land in L2-resident lines (window ~5us << L2 turnover).
__global__ void __launch_bounds__(THREADS) bloom_zp_kernel(
        const int* __restrict__ hashes, float* __restrict__ out) {
    const int slab = blockIdx.x;
    const int m0   = (slab & (SPB - 1)) * MRANGE;
    const int k    = (slab >> 7) % KBLK;
    const int b    = slab / (KBLK * SPB);           // slab / 640
    const int t    = threadIdx.x;

    // Issue the hash loads early; consumed after phase 1 (L2-resident input).
    const int4* hp = (const int4*)(hashes + (b * SS + t) * NH);
    const int4 h0 = __ldg(hp);
    const int4 h1 = __ldg(hp + 1);

    // Slab base: row (b*KBLK + k)*MB + m0, column 0.
    float* const slab_base =
        out + ((long long)(b * KBLK + k) * MB + m0) * SS;

    // ---- Phase 1: zero 4096 float4 = 64KB, contiguous -------------------
    {
        float4* p = (float4*)slab_base + t;
        const float4 z = make_float4(0.f, 0.f, 0.f, 0.f);
#pragma unroll
        for (int u = 0; u < (MRANGE * SS / 4) / THREADS; ++u)   // 8 stores
            p[u * THREADS] = z;          // compile-time imm offsets
    }

    __syncthreads();   // order phase-1 stores before phase-2 patch stores

    // ---- Phase 2: patch nonzeros from registers -------------------------
    const int j = t + 2 - k;               // output column for s = t
    if (j >= 0 && j < SS) {
        const int mm[8] = {h0.x & (MB - 1), h0.y & (MB - 1),
                           h0.z & (MB - 1), h0.w & (MB - 1),
                           h1.x & (MB - 1), h1.y & (MB - 1),
                           h1.z & (MB - 1), h1.w & (MB - 1)};
#pragma unroll
        for (int n = 0; n < NH; ++n) {
            const unsigned r = (unsigned)(mm[n] - m0);
            if (r < MRANGE) {
                int cnt = 0;
#pragma unroll
                for (int n2 = 0; n2 < NH; ++n2) cnt += (mm[n2] == mm[n]);
                // duplicate hashes write the same value -> idempotent
                slab_base[(long long)r * SS + j] = (float)cnt;
            }
        }
    }
}

extern "C" void kernel_launch(void* const* d_in, const int* in_sizes, int n_in,
                              void* d_out, int out_size) {
    const int* hashes = (const int*)d_in[0];
    float* out = (float*)d_out;
    bloom_zp_kernel<<<NSLAB, THREADS>>>(hashes, out);
}

// round 7
// speedup vs baseline: 1.4738x; 1.0073x over previous
#include <cuda_runtime.h>
#include <cuda_bf16.h>

// Problem constants (fixed by the reference)
#define BB      16
#define SS      512
#define NH      8
#define MB      4096
#define KBLK    5                       // 2*W+1
#define MRANGE  16                      // rows per slab -> 16*2KB = 32KB contiguous
#define SPB     (MB / MRANGE)           // 256 slabs per (b,k) block
#define NSLAB   (BB * KBLK * SPB)       // 16*5*256 = 20480
#define THREADS 512

// One CTA per slab = 16 contiguous output rows of one (b,k) block.
// Phase 1: zero the contiguous 32KB slab (4 dependency-free STG.128/thread).
// Phase 2: thread t (= sentence position s) patches its in-range hashes with
//          counts from 8-way register comparison. __syncthreads() (CTA-scope
//          memory fence) orders phase-1 stores before patch stores; patches
//          land in L2-resident lines (zero->patch window ~2us << L2 turnover).
__global__ void __launch_bounds__(THREADS) bloom_zp_kernel(
        const int* __restrict__ hashes, float* __restrict__ out) {
    const int slab = blockIdx.x;
    const int m0   = (slab & (SPB - 1)) * MRANGE;
    const int k    = (slab >> 8) % KBLK;
    const int b    = slab / (KBLK * SPB);           // slab / 1280
    const int t    = threadIdx.x;

    // Issue the hash loads early; consumed after phase 1 (L2-resident input).
    const int4* hp = (const int4*)(hashes + (b * SS + t) * NH);
    const int4 h0 = __ldg(hp);
    const int4 h1 = __ldg(hp + 1);

    // Slab base: row (b*KBLK + k)*MB + m0, column 0.
    float* const slab_base =
        out + ((long long)(b * KBLK + k) * MB + m0) * SS;

    // ---- Phase 1: zero 2048 float4 = 32KB, contiguous -------------------
    {
        float4* p = (float4*)slab_base + t;
        const float4 z = make_float4(0.f, 0.f, 0.f, 0.f);
#pragma unroll
        for (int u = 0; u < (MRANGE * SS / 4) / THREADS; ++u)   // 4 stores
            p[u * THREADS] = z;          // compile-time imm offsets
    }

    __syncthreads();   // order phase-1 stores before phase-2 patch stores

    // ---- Phase 2: patch nonzeros from registers -------------------------
    const int j = t + 2 - k;               // output column for s = t
    if (j >= 0 && j < SS) {
        const int mm[8] = {h0.x & (MB - 1), h0.y & (MB - 1),
                           h0.z & (MB - 1), h0.w & (MB - 1),
                           h1.x & (MB - 1), h1.y & (MB - 1),
                           h1.z & (MB - 1), h1.w & (MB - 1)};
#pragma unroll
        for (int n = 0; n < NH; ++n) {
            const unsigned r = (unsigned)(mm[n] - m0);
            if (r < MRANGE) {
                int cnt = 0;
#pragma unroll
                for (int n2 = 0; n2 < NH; ++n2) cnt += (mm[n2] == mm[n]);
                // duplicate hashes write the same value -> idempotent
                slab_base[(long long)r * SS + j] = (float)cnt;
            }
        }
    }
}

extern "C" void kernel_launch(void* const* d_in, const int* in_sizes, int n_in,
                              void* d_out, int out_size) {
    const int* hashes = (const int*)d_in[0];
    float* out = (float*)d_out;
    bloom_zp_kernel<<<NSLAB, THREADS>>>(hashes, out);
}